// round 6
// baseline (speedup 1.0000x reference)
#include <cuda_runtime.h>
#include <cstdint>
#include <cstddef>

// out[b,t,k,n,o] = sum_i x[b,t,n,i] * Wqkv[k, perm[phase,k,n], i, o]
// 64 GEMMs of [2048,1024]x[1024,192] fp32. tf32 mma.sync.m16n8k8 (cvt.rna).
// R6: staging via cp.async.bulk (192 bulk copies/chunk, mbarrier complete_tx)
// instead of 5120 LDGSTS/chunk; compute path identical to the 360us R4 kernel.

namespace {

constexpr int N_ = 16, IN_ = 1024, K_ = 4, D3_ = 192;
constexpr int M_TOTAL = 2048;
constexpr int TILE_M = 128;
constexpr int KC = 64;                    // K per chunk
constexpr int NCHUNK = IN_ / KC;          // 16
constexpr int ROWSTR = N_ * IN_;          // 16384 floats
constexpr int NTHREADS = 256;

// smem: mbarriers @0 (full[0]@0, full[1]@8), stages @64
constexpr int STAGE_BASE = 64;
constexpr int A_STRIDE = 272;             // 256 + 16 pad -> conflict-free frags
constexpr int B_STRIDE = 800;             // 768 + 32 pad -> conflict-free frags
constexpr int A_BYTES  = TILE_M * A_STRIDE;   // 34816
constexpr int B_BYTES  = KC * B_STRIDE;       // 51200
constexpr int STAGE_SZ = A_BYTES + B_BYTES;   // 86016
constexpr int SMEM_TOTAL = STAGE_BASE + 2 * STAGE_SZ;  // 172096
constexpr uint32_t CHUNK_TX = 128 * 256 + 64 * 768;    // 81920 bytes

__device__ __forceinline__ uint32_t smem_u32(const void* p) {
    uint32_t a;
    asm("{ .reg .u64 t; cvta.to.shared.u64 t, %1; cvt.u32.u64 %0, t; }"
        : "=r"(a) : "l"(p));
    return a;
}

__device__ __forceinline__ void mbar_init(uint32_t a, uint32_t cnt) {
    asm volatile("mbarrier.init.shared.b64 [%0], %1;" :: "r"(a), "r"(cnt) : "memory");
}
__device__ __forceinline__ void mbar_expect_tx(uint32_t a, uint32_t bytes) {
    asm volatile("mbarrier.arrive.expect_tx.shared.b64 _, [%0], %1;"
                 :: "r"(a), "r"(bytes) : "memory");
}
__device__ __forceinline__ void mbar_wait(uint32_t a, uint32_t parity) {
    uint32_t done;
    asm volatile(
        "{\n\t.reg .pred p;\n\t"
        "mbarrier.try_wait.parity.acquire.cta.shared::cta.b64 p, [%1], %2;\n\t"
        "selp.b32 %0, 1, 0, p;\n\t}"
        : "=r"(done) : "r"(a), "r"(parity) : "memory");
    if (!done) {
        asm volatile(
            "{\n\t.reg .pred P1;\n\t"
            "WL_%=:\n\t"
            "mbarrier.try_wait.parity.acquire.cta.shared::cta.b64 P1, [%0], %1, 0x989680;\n\t"
            "@P1 bra.uni WD_%=;\n\t"
            "bra.uni WL_%=;\n\t"
            "WD_%=:\n\t}"
            :: "r"(a), "r"(parity) : "memory");
    }
}

__device__ __forceinline__ void bulk_g2s(uint32_t dst, const void* src,
                                         uint32_t bytes, uint32_t mbar) {
    asm volatile(
        "cp.async.bulk.shared::cluster.global.mbarrier::complete_tx::bytes "
        "[%0], [%1], %2, [%3];"
        :: "r"(dst), "l"(src), "r"(bytes), "r"(mbar) : "memory");
}

__device__ __forceinline__ uint32_t f2tf32(float f) {
    uint32_t r;
    asm("cvt.rna.tf32.f32 %0, %1;" : "=r"(r) : "f"(f));
    return r;
}

__device__ __forceinline__ void mma_tf32(float* d,
                                         uint32_t a0, uint32_t a1,
                                         uint32_t a2, uint32_t a3,
                                         uint32_t b0, uint32_t b1) {
    asm volatile(
        "mma.sync.aligned.m16n8k8.row.col.f32.tf32.tf32.f32 "
        "{%0,%1,%2,%3}, {%4,%5,%6,%7}, {%8,%9}, {%0,%1,%2,%3};"
        : "+f"(d[0]), "+f"(d[1]), "+f"(d[2]), "+f"(d[3])
        : "r"(a0), "r"(a1), "r"(a2), "r"(a3), "r"(b0), "r"(b1));
}

} // namespace

__global__ void __launch_bounds__(NTHREADS, 1)
qkv_tf32_kernel(const float* __restrict__ x, const float* __restrict__ W,
                const int* __restrict__ perm32,
                const int* __restrict__ phase_p,
                float* __restrict__ out)
{
    extern __shared__ char sm[];
    const uint32_t smb = smem_u32(sm);
    const int tid = threadIdx.x;
    const int wid = tid >> 5;
    const int lid = tid & 31;
    const int gid = lid >> 2;               // groupID 0..7
    const int tg  = lid & 3;                // threadID_in_group 0..3

    const int tile_m = blockIdx.x;          // 0..15
    const int pair   = blockIdx.y;          // 0..63
    const int n = pair >> 2;
    const int k = pair & 3;
    const int m0 = tile_m * TILE_M;

    // ---- dtype-robust perm read (jnp.int64 may silently be int32) ----
    const int phase = __ldg(phase_p) & 0xFFFF;
    const bool is64 = (__ldg(perm32 + 1) == 0) &&
                      (__ldg(perm32 + 3) == 0) &&
                      (__ldg(perm32 + 5) == 0);
    const int pidx = phase * (K_ * N_) + k * N_ + n;
    int pm = __ldg(perm32 + (is64 ? 2 * pidx : pidx));
    pm &= 15;

    const float* __restrict__ Wb =
        W + ((size_t)k * N_ + (size_t)pm) * (size_t)(IN_ * D3_);
    const float* __restrict__ Xb =
        x + (size_t)n * IN_ + (size_t)m0 * ROWSTR;

    // warp grid 2 (m) x 4 (n): warp tile 64 x 48
    const int wm = wid >> 2;
    const int wn = wid & 3;
    const int m_base = wm * 64;
    const int n_base = wn * 48;

    float acc[4][6][4];
    #pragma unroll
    for (int mt = 0; mt < 4; ++mt)
        #pragma unroll
        for (int nt = 0; nt < 6; ++nt)
            #pragma unroll
            for (int r = 0; r < 4; ++r) acc[mt][nt][r] = 0.0f;

    // ---- mbarrier init ----
    if (tid == 0) {
        mbar_init(smb + 0, 1);      // full[0]: 1 arrive (the expect_tx)
        mbar_init(smb + 8, 1);      // full[1]
    }
    __syncthreads();

    // ---- bulk staging: warp 0 issues 192 bulk copies per chunk ----
    auto issue_chunk = [&](int c) {
        const int s = c & 1;
        const uint32_t mb = smb + s * 8;
        const uint32_t st = smb + STAGE_BASE + s * STAGE_SZ;
        const int kk = c * KC;
        if (lid == 0) mbar_expect_tx(mb, CHUNK_TX);
        __syncwarp();
        // A: 128 rows x 256B
        #pragma unroll
        for (int it = 0; it < 4; ++it) {
            const int r = lid + it * 32;
            bulk_g2s(st + r * A_STRIDE,
                     Xb + (size_t)r * ROWSTR + kk, 256, mb);
        }
        // B: 64 rows x 768B
        #pragma unroll
        for (int it = 0; it < 2; ++it) {
            const int r = lid + it * 32;
            bulk_g2s(st + A_BYTES + r * B_STRIDE,
                     Wb + (size_t)(kk + r) * D3_, 768, mb);
        }
    };

    if (wid == 0) {
        issue_chunk(0);
        issue_chunk(1);
    }

    for (int c = 0; c < NCHUNK; ++c) {
        const int s = c & 1;
        mbar_wait(smb + s * 8, (uint32_t)((c >> 1) & 1));

        const char* sa = sm + STAGE_BASE + s * STAGE_SZ;
        const char* sb = sa + A_BYTES;
        const char* sa_r0 = sa + (m_base + gid) * A_STRIDE;
        const char* sb_c  = sb + (n_base + gid) * 4;

        #pragma unroll
        for (int ks = 0; ks < 8; ++ks) {
            const int i0 = ks * 8 + tg;
            uint32_t af[4][4];
            #pragma unroll
            for (int mt = 0; mt < 4; ++mt) {
                const char* p = sa_r0 + mt * 16 * A_STRIDE + i0 * 4;
                af[mt][0] = f2tf32(*(const float*)(p));
                af[mt][1] = f2tf32(*(const float*)(p + 8 * A_STRIDE));
                af[mt][2] = f2tf32(*(const float*)(p + 16));
                af[mt][3] = f2tf32(*(const float*)(p + 8 * A_STRIDE + 16));
            }
            #pragma unroll
            for (int nt = 0; nt < 6; ++nt) {
                const char* q = sb_c + i0 * B_STRIDE + nt * 32;
                const uint32_t b0 = f2tf32(*(const float*)(q));
                const uint32_t b1 = f2tf32(*(const float*)(q + 4 * B_STRIDE));
                #pragma unroll
                for (int mt = 0; mt < 4; ++mt)
                    mma_tf32(acc[mt][nt],
                             af[mt][0], af[mt][1], af[mt][2], af[mt][3], b0, b1);
            }
        }
        __syncthreads();                      // all readers done with stage s
        if (c + 2 < NCHUNK && wid == 0) issue_chunk(c + 2);
    }

    // ---- epilogue ----
    #pragma unroll
    for (int mt = 0; mt < 4; ++mt) {
        const size_t r0 = (size_t)(m0 + m_base + mt * 16 + gid);
        const size_t r1 = r0 + 8;
        float* ob0 = out + (((r0 * K_ + (size_t)k) * N_) + (size_t)n) * (size_t)D3_;
        float* ob1 = out + (((r1 * K_ + (size_t)k) * N_) + (size_t)n) * (size_t)D3_;
        #pragma unroll
        for (int nt = 0; nt < 6; ++nt) {
            const int col = n_base + nt * 8 + tg * 2;
            *(float2*)(ob0 + col) = make_float2(acc[mt][nt][0], acc[mt][nt][1]);
            *(float2*)(ob1 + col) = make_float2(acc[mt][nt][2], acc[mt][nt][3]);
        }
    }
}

extern "C" void kernel_launch(void* const* d_in, const int* in_sizes, int n_in,
                              void* d_out, int out_size) {
    const float* x     = (const float*)d_in[0];
    const float* Wqkv  = (const float*)d_in[1];
    const int* perm32  = (const int*)d_in[2];      // int32 OR int64 (sniffed)
    // d_in[3] = invperm (unused)
    const int* phase   = (const int*)d_in[4];
    float* out         = (float*)d_out;

    cudaFuncSetAttribute(qkv_tf32_kernel,
                         cudaFuncAttributeMaxDynamicSharedMemorySize, SMEM_TOTAL);
    dim3 grid(M_TOTAL / TILE_M, K_ * N_);   // (16, 64)
    qkv_tf32_kernel<<<grid, NTHREADS, SMEM_TOTAL>>>(x, Wqkv, perm32, phase, out);
}

// round 7
// speedup vs baseline: 2.7475x; 2.7475x over previous
#include <cuda_runtime.h>
#include <cuda.h>
#include <cstdint>
#include <cstddef>

// out[b,t,k,n,o] = sum_i x[b,t,n,i] * Wqkv[k, perm[phase,k,n], i, o]
// 64 GEMMs of [2048,1024]x[1024,192] fp32. tf32 mma.sync.m16n8k8 (cvt.rna).
// R7: staging via TMA tensor maps (7 UTMALDG per chunk vs 5120 LDGSTS),
// 4-stage mbarrier pipeline, barrier-free mainloop. Compute path = R4 (360us).

namespace {

constexpr int N_ = 16, IN_ = 1024, K_ = 4, D3_ = 192;
constexpr int M_TOTAL = 2048;
constexpr int TILE_M = 128;
constexpr int KC = 32;                     // K per chunk (128B f32 = SW128 box)
constexpr int NCHUNK = IN_ / KC;           // 32
constexpr int NSTAGE = 4;

// smem: full[4] mbar @0, empty[4] mbar @64, stages @1024 (1024-aligned for SW128)
constexpr int STAGE_BASE = 1024;
constexpr int A_SZ = TILE_M * KC * 4;      // 16384: A [128 m][32 i] swizzled
constexpr int B_SZ = 6 * 32 * KC * 4;      // 24576: B 6 blocks [32 i][32 o]
constexpr int STAGE_SZ = A_SZ + B_SZ;      // 40960
constexpr int SMEM_TOTAL = STAGE_BASE + NSTAGE * STAGE_SZ;  // 164864
constexpr uint32_t CHUNK_TX = (uint32_t)STAGE_SZ;

__device__ __forceinline__ uint32_t smem_u32(const void* p) {
    uint32_t a;
    asm("{ .reg .u64 t; cvta.to.shared.u64 t, %1; cvt.u32.u64 %0, t; }"
        : "=r"(a) : "l"(p));
    return a;
}

__device__ __forceinline__ void mbar_init(uint32_t a, uint32_t cnt) {
    asm volatile("mbarrier.init.shared.b64 [%0], %1;" :: "r"(a), "r"(cnt) : "memory");
}
__device__ __forceinline__ void mbar_arrive(uint32_t a) {
    asm volatile("mbarrier.arrive.shared.b64 _, [%0];" :: "r"(a) : "memory");
}
__device__ __forceinline__ void mbar_expect_tx(uint32_t a, uint32_t bytes) {
    asm volatile("mbarrier.arrive.expect_tx.shared.b64 _, [%0], %1;"
                 :: "r"(a), "r"(bytes) : "memory");
}
__device__ __forceinline__ void mbar_wait(uint32_t a, uint32_t parity) {
    uint32_t done;
    asm volatile(
        "{\n\t.reg .pred p;\n\t"
        "mbarrier.try_wait.parity.acquire.cta.shared::cta.b64 p, [%1], %2;\n\t"
        "selp.b32 %0, 1, 0, p;\n\t}"
        : "=r"(done) : "r"(a), "r"(parity) : "memory");
    if (!done) {
        asm volatile(
            "{\n\t.reg .pred P1;\n\t"
            "WL_%=:\n\t"
            "mbarrier.try_wait.parity.acquire.cta.shared::cta.b64 P1, [%0], %1, 0x989680;\n\t"
            "@P1 bra.uni WD_%=;\n\t"
            "bra.uni WL_%=;\n\t"
            "WD_%=:\n\t}"
            :: "r"(a), "r"(parity) : "memory");
    }
}

__device__ __forceinline__ void tma3(uint32_t dst, const CUtensorMap* map,
                                     int c0, int c1, int c2, uint32_t mbar) {
    asm volatile(
        "cp.async.bulk.tensor.3d.shared::cta.global.tile.mbarrier::complete_tx::bytes "
        "[%0], [%1, {%2, %3, %4}], [%5];"
        :: "r"(dst), "l"(map), "r"(c0), "r"(c1), "r"(c2), "r"(mbar) : "memory");
}

__device__ __forceinline__ uint32_t f2tf32(float f) {
    uint32_t r;
    asm("cvt.rna.tf32.f32 %0, %1;" : "=r"(r) : "f"(f));
    return r;
}

__device__ __forceinline__ void mma_tf32(float* d,
                                         uint32_t a0, uint32_t a1,
                                         uint32_t a2, uint32_t a3,
                                         uint32_t b0, uint32_t b1) {
    asm volatile(
        "mma.sync.aligned.m16n8k8.row.col.f32.tf32.tf32.f32 "
        "{%0,%1,%2,%3}, {%4,%5,%6,%7}, {%8,%9}, {%0,%1,%2,%3};"
        : "+f"(d[0]), "+f"(d[1]), "+f"(d[2]), "+f"(d[3])
        : "r"(a0), "r"(a1), "r"(a2), "r"(a3), "r"(b0), "r"(b1));
}

} // namespace

__global__ void __launch_bounds__(256, 1)
qkv_tma_kernel(const int* __restrict__ perm32,
               const int* __restrict__ phase_p,
               float* __restrict__ out,
               const __grid_constant__ CUtensorMap tmA,
               const __grid_constant__ CUtensorMap tmB)
{
    extern __shared__ char sm[];
    const uint32_t smb = smem_u32(sm);
    const int tid = threadIdx.x;
    const int wid = tid >> 5;
    const int lid = tid & 31;
    const int gid = lid >> 2;               // groupID 0..7
    const int tg  = lid & 3;                // threadID_in_group 0..3

    const int tile_m = blockIdx.x;          // 0..15
    const int pair   = blockIdx.y;          // 0..63
    const int n = pair >> 2;
    const int k = pair & 3;
    const int m0 = tile_m * TILE_M;

    // ---- dtype-robust perm read (jnp.int64 may silently be int32) ----
    const int phase = __ldg(phase_p) & 0xFFFF;
    const bool is64 = (__ldg(perm32 + 1) == 0) &&
                      (__ldg(perm32 + 3) == 0) &&
                      (__ldg(perm32 + 5) == 0);
    const int pidx = phase * (K_ * N_) + k * N_ + n;
    int pm = __ldg(perm32 + (is64 ? 2 * pidx : pidx));
    pm &= 15;
    const int kn = k * N_ + pm;             // W plane index for TMA coord

    // warp grid 2 (m) x 4 (n): warp tile 64 x 48
    const int wm = wid >> 2;
    const int wn = wid & 3;
    const int m_base = wm * 64;
    const int n_base = wn * 48;

    // per-thread SW128 xor masks (row&7 is thread-constant for our fragments)
    const uint32_t mAx  = (uint32_t)gid << 4;        // A rows: row&7 == gid
    const uint32_t mB0x = (uint32_t)tg << 4;         // B i-row & 7 == tg
    const uint32_t mB1x = (uint32_t)(tg + 4) << 4;   // i+4

    float acc[4][6][4];
    #pragma unroll
    for (int mt = 0; mt < 4; ++mt)
        #pragma unroll
        for (int nt = 0; nt < 6; ++nt)
            #pragma unroll
            for (int r = 0; r < 4; ++r) acc[mt][nt][r] = 0.0f;

    // ---- mbarrier init: full[s] count 1 (expect_tx), empty[s] count 256 ----
    if (tid == 0) {
        #pragma unroll
        for (int s = 0; s < NSTAGE; ++s) {
            mbar_init(smb + s * 8, 1);
            mbar_init(smb + 64 + s * 8, 256);
        }
    }
    __syncthreads();

    // ---- producer: 7 TMA loads per chunk ----
    auto issue = [&](int cc) {
        const int s = cc & 3;
        const uint32_t mb = smb + s * 8;
        const uint32_t st = smb + STAGE_BASE + s * STAGE_SZ;
        const int i0 = cc * KC;
        mbar_expect_tx(mb, CHUNK_TX);
        tma3(st, &tmA, i0, n, m0, mb);                       // A [32 i][1 n][128 m]
        #pragma unroll
        for (int ob = 0; ob < 6; ++ob)                       // B [32 o][32 i][plane]
            tma3(st + A_SZ + ob * 4096, &tmB, ob * 32, i0, kn, mb);
    };

    if (tid == 0) {
        issue(0); issue(1); issue(2);
    }

    for (int c = 0; c < NCHUNK; ++c) {
        if (tid == 0) {
            const int cc = c + NSTAGE - 1;
            if (cc < NCHUNK) {
                const int p = cc >> 2;
                if (p > 0) mbar_wait(smb + 64 + (cc & 3) * 8, (uint32_t)((p - 1) & 1));
                issue(cc);
            }
        }
        const int s = c & 3;
        mbar_wait(smb + s * 8, (uint32_t)((c >> 2) & 1));

        const char* sa = sm + STAGE_BASE + s * STAGE_SZ;
        const char* sbb = sa + A_SZ;

        #pragma unroll
        for (int ks = 0; ks < 4; ++ks) {
            const uint32_t i4 = (uint32_t)(ks * 32 + tg * 4);   // i_local*4
            uint32_t af[4][4];
            #pragma unroll
            for (int mt = 0; mt < 4; ++mt) {
                const char* p = sa + (m_base + mt * 16 + gid) * 128;
                af[mt][0] = f2tf32(*(const float*)(p + (i4 ^ mAx)));
                af[mt][1] = f2tf32(*(const float*)(p + 1024 + (i4 ^ mAx)));
                af[mt][2] = f2tf32(*(const float*)(p + ((i4 + 16) ^ mAx)));
                af[mt][3] = f2tf32(*(const float*)(p + 1024 + ((i4 + 16) ^ mAx)));
            }
            #pragma unroll
            for (int nt = 0; nt < 6; ++nt) {
                const int oabs = n_base + nt * 8;           // 8-aligned, no block cross
                const char* q = sbb + (oabs >> 5) * 4096 + ks * 1024 + tg * 128;
                const uint32_t og4 = (uint32_t)(((oabs & 31) + gid) * 4);
                const uint32_t b0 = f2tf32(*(const float*)(q + (og4 ^ mB0x)));
                const uint32_t b1 = f2tf32(*(const float*)(q + 512 - tg * 128 +
                                                           (tg + 4) * 128 - 512 +
                                                           512 + (og4 ^ mB1x) - (tg + 4) * 128 + tg * 128));
                // NOTE: simplified below — kept explicit form:
                (void)b1;
                const uint32_t b1v = f2tf32(*(const float*)(sbb + (oabs >> 5) * 4096 +
                                                            ks * 1024 + (tg + 4) * 128 +
                                                            (og4 ^ mB1x)));
                #pragma unroll
                for (int mt = 0; mt < 4; ++mt)
                    mma_tf32(acc[mt][nt],
                             af[mt][0], af[mt][1], af[mt][2], af[mt][3], b0, b1v);
            }
        }
        mbar_arrive(smb + 64 + s * 8);
    }

    // ---- epilogue ----
    #pragma unroll
    for (int mt = 0; mt < 4; ++mt) {
        const size_t r0 = (size_t)(m0 + m_base + mt * 16 + gid);
        const size_t r1 = r0 + 8;
        float* ob0 = out + (((r0 * K_ + (size_t)k) * N_) + (size_t)n) * (size_t)D3_;
        float* ob1 = out + (((r1 * K_ + (size_t)k) * N_) + (size_t)n) * (size_t)D3_;
        #pragma unroll
        for (int nt = 0; nt < 6; ++nt) {
            const int col = n_base + nt * 8 + tg * 2;
            *(float2*)(ob0 + col) = make_float2(acc[mt][nt][0], acc[mt][nt][1]);
            *(float2*)(ob1 + col) = make_float2(acc[mt][nt][2], acc[mt][nt][3]);
        }
    }
}

extern "C" void kernel_launch(void* const* d_in, const int* in_sizes, int n_in,
                              void* d_out, int out_size) {
    const float* x     = (const float*)d_in[0];
    const float* Wqkv  = (const float*)d_in[1];
    const int* perm32  = (const int*)d_in[2];      // int32 OR int64 (sniffed)
    // d_in[3] = invperm (unused)
    const int* phase   = (const int*)d_in[4];
    float* out         = (float*)d_out;

    // ---- build TMA tensor maps (host, capture-safe) ----
    typedef CUresult (*EncFn)(CUtensorMap*, CUtensorMapDataType, cuuint32_t, void*,
                              const cuuint64_t*, const cuuint64_t*,
                              const cuuint32_t*, const cuuint32_t*,
                              CUtensorMapInterleave, CUtensorMapSwizzle,
                              CUtensorMapL2promotion, CUtensorMapFloatOOBfill);
    EncFn enc = nullptr;
    cudaDriverEntryPointQueryResult qst;
#if CUDART_VERSION >= 12050
    cudaGetDriverEntryPointByVersion("cuTensorMapEncodeTiled", (void**)&enc,
                                     12000, cudaEnableDefault, &qst);
#else
    cudaGetDriverEntryPoint("cuTensorMapEncodeTiled", (void**)&enc,
                            cudaEnableDefault, &qst);
#endif
    CUtensorMap tmA, tmB;
    {
        cuuint64_t dims[3]    = {(cuuint64_t)IN_, (cuuint64_t)N_, (cuuint64_t)M_TOTAL};
        cuuint64_t strides[2] = {(cuuint64_t)IN_ * 4, (cuuint64_t)N_ * IN_ * 4};
        cuuint32_t box[3]     = {32, 1, 128};
        cuuint32_t es[3]      = {1, 1, 1};
        enc(&tmA, CU_TENSOR_MAP_DATA_TYPE_FLOAT32, 3, (void*)x,
            dims, strides, box, es,
            CU_TENSOR_MAP_INTERLEAVE_NONE, CU_TENSOR_MAP_SWIZZLE_128B,
            CU_TENSOR_MAP_L2_PROMOTION_L2_128B, CU_TENSOR_MAP_FLOAT_OOB_FILL_NONE);
    }
    {
        cuuint64_t dims[3]    = {(cuuint64_t)D3_, (cuuint64_t)IN_, (cuuint64_t)(K_ * N_)};
        cuuint64_t strides[2] = {(cuuint64_t)D3_ * 4, (cuuint64_t)IN_ * D3_ * 4};
        cuuint32_t box[3]     = {32, 32, 1};
        cuuint32_t es[3]      = {1, 1, 1};
        enc(&tmB, CU_TENSOR_MAP_DATA_TYPE_FLOAT32, 3, (void*)Wqkv,
            dims, strides, box, es,
            CU_TENSOR_MAP_INTERLEAVE_NONE, CU_TENSOR_MAP_SWIZZLE_128B,
            CU_TENSOR_MAP_L2_PROMOTION_L2_128B, CU_TENSOR_MAP_FLOAT_OOB_FILL_NONE);
    }

    cudaFuncSetAttribute(qkv_tma_kernel,
                         cudaFuncAttributeMaxDynamicSharedMemorySize, SMEM_TOTAL);
    dim3 grid(M_TOTAL / TILE_M, K_ * N_);   // (16, 64)
    qkv_tma_kernel<<<grid, 256, SMEM_TOTAL>>>(perm32, phase, out, tmA, tmB);
}